// round 8
// baseline (speedup 1.0000x reference)
#include <cuda_runtime.h>
#include <cstdint>

#define N_NODES 100000
#define N_EDGES 1250000
#define DIM 64
#define NBASES 16
#define E_HALF (N_EDGES / 2)
#define N_TILES ((N_NODES + 63) / 64)   // 1563

// ---------------- scratch (device globals; no allocation allowed) ----------
__device__ float g_S[(size_t)N_NODES * DIM];          // scatter-sum of x[src]; self-zeroed by out_kernel
__device__ float g_deg[N_NODES];                      // in-degree; self-zeroed by out_kernel
__device__ __align__(16) float2 g_Bp[64 * 64];        // k-pair-packed B: [kp][c] = (B[2kp][c], B[2kp+1][c])
__device__ float g_bm[DIM];
__device__ float g_bs[DIM];

// packed f32x2 FMA: d.lo += a.lo*b.lo ; d.hi += a.hi*b.hi
__device__ __forceinline__ void fma2(unsigned long long& d,
                                     unsigned long long a,
                                     unsigned long long b) {
    asm("fma.rn.f32x2 %0, %1, %2, %0;" : "+l"(d) : "l"(a), "l"(b));
}
__device__ __forceinline__ float pair_sum(unsigned long long v) {
    return __uint_as_float((unsigned)(v & 0xffffffffull)) +
           __uint_as_float((unsigned)(v >> 32));
}

// ---------------- kernel 1: collapse bases into packed weights -------------
// 17 blocks x 256 threads (round-5 proven: ~5us).
__global__ __launch_bounds__(256) void weights_kernel(
    const float* __restrict__ wm, const float* __restrict__ bm,
    const float* __restrict__ ws, const float* __restrict__ bs,
    const float* __restrict__ lc) {
    __shared__ float c[NBASES];
    if (threadIdx.x < NBASES) c[threadIdx.x] = lc[threadIdx.x];
    __syncthreads();

    if (blockIdx.x < 16) {
        int idx = blockIdx.x * 256 + threadIdx.x;   // 0..4095
        int kp = idx >> 6;
        int o  = idx & 63;
        const float* base = (kp < 32) ? wm : ws;
        int i0 = (kp < 32) ? 2 * kp : 2 * (kp - 32);
        const float4* p0 = reinterpret_cast<const float4*>(&base[((size_t)i0 * 64 + o) * NBASES]);
        const float4* p1 = reinterpret_cast<const float4*>(&base[((size_t)(i0 + 1) * 64 + o) * NBASES]);
        float lo = 0.f, hi = 0.f;
        #pragma unroll
        for (int q = 0; q < 4; q++) {               // 16 bases as 4x float4 (MLP)
            float4 a0 = __ldg(&p0[q]);
            float4 a1 = __ldg(&p1[q]);
            lo = fmaf(a0.x, c[4*q+0], lo); lo = fmaf(a0.y, c[4*q+1], lo);
            lo = fmaf(a0.z, c[4*q+2], lo); lo = fmaf(a0.w, c[4*q+3], lo);
            hi = fmaf(a1.x, c[4*q+0], hi); hi = fmaf(a1.y, c[4*q+1], hi);
            hi = fmaf(a1.z, c[4*q+2], hi); hi = fmaf(a1.w, c[4*q+3], hi);
        }
        g_Bp[idx] = make_float2(lo, hi);
    } else if (threadIdx.x < DIM) {
        int tid = threadIdx.x;
        float am = 0.f, as = 0.f;
        #pragma unroll
        for (int b = 0; b < NBASES; b++) {
            am = fmaf(__ldg(&bm[tid * NBASES + b]), c[b], am);
            as = fmaf(__ldg(&bs[tid * NBASES + b]), c[b], as);
        }
        g_bm[tid] = am;
        g_bs[tid] = as;
    }
}

// ---------------- kernel 2: edge scatter (S[dst] += x[src], deg[dst]++) ----
// 16 threads per edge-PAIR (edges e and e+E_HALF), float4 granularity, ILP 2.
// ~52us, near the L2 atomic-ALU floor (~30-40us) — leave alone.
__global__ __launch_bounds__(256) void scatter_kernel(
    const float4* __restrict__ x4, const int* __restrict__ ei) {
    int t = blockIdx.x * blockDim.x + threadIdx.x;
    int e = t >> 4;
    if (e >= E_HALF) return;
    int sub = t & 15;
    int e2 = e + E_HALF;
    int src1 = __ldg(&ei[e]);
    int dst1 = __ldg(&ei[N_EDGES + e]);
    int src2 = __ldg(&ei[e2]);
    int dst2 = __ldg(&ei[N_EDGES + e2]);
    float4 v1 = __ldg(&x4[(size_t)src1 * 16 + sub]);
    float4 v2 = __ldg(&x4[(size_t)src2 * 16 + sub]);
    float* p1 = &g_S[(size_t)dst1 * DIM + sub * 4];
    float* p2 = &g_S[(size_t)dst2 * DIM + sub * 4];
    asm volatile("red.global.add.v4.f32 [%0], {%1, %2, %3, %4};"
                 :: "l"(p1), "f"(v1.x), "f"(v1.y), "f"(v1.z), "f"(v1.w) : "memory");
    asm volatile("red.global.add.v4.f32 [%0], {%1, %2, %3, %4};"
                 :: "l"(p2), "f"(v2.x), "f"(v2.y), "f"(v2.z), "f"(v2.w) : "memory");
    if (sub == 0) {
        atomicAdd(&g_deg[dst1], 1.0f);
        atomicAdd(&g_deg[dst2], 1.0f);
    }
}

// ---------------- kernel 3: out = [S|x] @ [Wm;Ws] + deg*bm + bs, L2-norm ---
// One block per 64-node tile. 256 threads, each 4 rows x 4 cols, f32x2 math.
// B staged in SHARED (keeps B off the LSU; LDS pipe is otherwise idle).
// __launch_bounds__(256,3): 84-reg cap -> 3 blocks/SM (24 warps). Register
// budget acc32+av16+B16+idx~14 = ~80 fits (round-6's 4-block/64-reg spilled;
// default bounds -> ~90 regs -> only 2 blocks: both measured slower).
// Self-cleans g_S/g_deg for the next launch.
__global__ __launch_bounds__(256, 3) void out_kernel(const float* __restrict__ x,
                                                     float* __restrict__ out) {
    __shared__ __align__(16) float2 sB[64 * 64];   // 32KB, same layout as g_Bp
    __shared__ float sbm[DIM], sbs[DIM];

    const int tid = threadIdx.x;

    // Stage B + biases (coalesced; 2048 float4)
    {
        const float4* gB4 = reinterpret_cast<const float4*>(g_Bp);
        float4* sB4 = reinterpret_cast<float4*>(sB);
        #pragma unroll
        for (int i = 0; i < 8; i++) sB4[tid + i * 256] = gB4[tid + i * 256];
        if (tid < DIM) { sbm[tid] = g_bm[tid]; sbs[tid] = g_bs[tid]; }
    }
    __syncthreads();

    const int jj = tid & 15;   // column group: cols j0..j0+3
    const int nn = tid >> 4;   // row group:   rows n0..n0+3
    const int j0 = jj * 4;
    const int n0 = nn * 4;
    const int node0 = blockIdx.x * 64;

    const ulonglong2* __restrict__ S2  = reinterpret_cast<const ulonglong2*>(g_S);
    const ulonglong2* __restrict__ X2  = reinterpret_cast<const ulonglong2*>(x);
    const ulonglong2* sB2 = reinterpret_cast<const ulonglong2*>(sB);
    const int bbase = j0 >> 1;  // ull2 index within a Bp row (32 ull2/row)

    int node[4];
    #pragma unroll
    for (int r = 0; r < 4; r++)
        node[r] = min(node0 + n0 + r, N_NODES - 1);   // clamp (last block only;
    // clamp is uniform within each 16-lane jj-group so norm shuffles stay valid)

    unsigned long long acc[4][4];
    #pragma unroll
    for (int r = 0; r < 4; r++)
        #pragma unroll
        for (int c2 = 0; c2 < 4; c2++) acc[r][c2] = 0ull;

    // ---- K half 1: A = S rows (k 0..63), B pair-rows kp 0..31 ----
    #pragma unroll 4
    for (int k4 = 0; k4 < 16; k4++) {
        ulonglong2 av[4];
        #pragma unroll
        for (int r = 0; r < 4; r++)
            av[r] = __ldg(&S2[(size_t)node[r] * 16 + k4]);
        #pragma unroll
        for (int p = 0; p < 2; p++) {
            int kp = k4 * 2 + p;
            ulonglong2 b01 = sB2[kp * 32 + bbase];
            ulonglong2 b23 = sB2[kp * 32 + bbase + 1];
            #pragma unroll
            for (int r = 0; r < 4; r++) {
                unsigned long long a = p ? av[r].y : av[r].x;
                fma2(acc[r][0], a, b01.x);
                fma2(acc[r][1], a, b01.y);
                fma2(acc[r][2], a, b23.x);
                fma2(acc[r][3], a, b23.y);
            }
        }
    }
    // ---- K half 2: A = x rows (k 64..127), B pair-rows kp 32..63 ----
    #pragma unroll 4
    for (int k4 = 0; k4 < 16; k4++) {
        ulonglong2 av[4];
        #pragma unroll
        for (int r = 0; r < 4; r++)
            av[r] = __ldg(&X2[(size_t)node[r] * 16 + k4]);
        #pragma unroll
        for (int p = 0; p < 2; p++) {
            int kp = 32 + k4 * 2 + p;
            ulonglong2 b01 = sB2[kp * 32 + bbase];
            ulonglong2 b23 = sB2[kp * 32 + bbase + 1];
            #pragma unroll
            for (int r = 0; r < 4; r++) {
                unsigned long long a = p ? av[r].y : av[r].x;
                fma2(acc[r][0], a, b01.x);
                fma2(acc[r][1], a, b01.y);
                fma2(acc[r][2], a, b23.x);
                fma2(acc[r][3], a, b23.y);
            }
        }
    }

    // Epilogue: fold halves, bias, row L2-norm (reduce across 16 jj lanes), store.
    #pragma unroll
    for (int r = 0; r < 4; r++) {
        float deg = __ldg(&g_deg[node[r]]);
        float o[4];
        #pragma unroll
        for (int c = 0; c < 4; c++)
            o[c] = pair_sum(acc[r][c]) + deg * sbm[j0 + c] + sbs[j0 + c];
        float ss = o[0] * o[0] + o[1] * o[1] + o[2] * o[2] + o[3] * o[3];
        #pragma unroll
        for (int off = 8; off > 0; off >>= 1)
            ss += __shfl_xor_sync(0xffffffffu, ss, off);   // stays within 16-lane half
        float inv = 1.0f / fmaxf(sqrtf(ss), 1e-12f);
        if (node0 + n0 + r < N_NODES) {
            float4 ov = make_float4(o[0] * inv, o[1] * inv, o[2] * inv, o[3] * inv);
            reinterpret_cast<float4*>(out)[(size_t)node[r] * 16 + jj] = ov;
        }
    }

    // Self-clean scratch for the next launch. All reads of these rows happened
    // above in this same 16-thread group; the shuffles ordered them.
    float4* S4 = reinterpret_cast<float4*>(g_S);
    #pragma unroll
    for (int r = 0; r < 4; r++) {
        if (node0 + n0 + r < N_NODES) {
            S4[(size_t)node[r] * 16 + jj] = make_float4(0.f, 0.f, 0.f, 0.f);
            if (jj == 0) g_deg[node[r]] = 0.f;
        }
    }
}

// ---------------- launch ----------------------------------------------------
extern "C" void kernel_launch(void* const* d_in, const int* in_sizes, int n_in,
                              void* d_out, int out_size) {
    const float* x  = (const float*)d_in[0];
    const int*   ei = (const int*)d_in[1];
    const float* wm = (const float*)d_in[2];
    const float* bm = (const float*)d_in[3];
    const float* ws = (const float*)d_in[4];
    const float* bs = (const float*)d_in[5];
    const float* lc = (const float*)d_in[6];
    float* out = (float*)d_out;

    // collapse bases into packed weights (17 parallel blocks)
    weights_kernel<<<17, 256>>>(wm, bm, ws, bs, lc);
    // edge scatter (g_S/g_deg are zero: BSS init on first call, self-cleaned after)
    {
        long long tot = (long long)E_HALF * 16;            // 10M threads
        int blocks = (int)((tot + 255) / 256);
        scatter_kernel<<<blocks, 256>>>((const float4*)x, ei);
    }
    // fused GEMM + bias + normalize + scratch self-clean (B in smem, 3 blk/SM)
    out_kernel<<<N_TILES, 256>>>(x, out);
}

// round 9
// speedup vs baseline: 1.0658x; 1.0658x over previous
#include <cuda_runtime.h>
#include <cstdint>

#define N_NODES 100000
#define N_EDGES 1250000
#define DIM 64
#define NBASES 16
#define N_TILES ((N_NODES + 63) / 64)   // 1563
#define SCAN_BLOCKS 98                  // ceil(100000 / 1024)

// ---------------- scratch (device globals; no allocation allowed) ----------
__device__ int g_cnt[N_NODES];          // per-dst edge count; zeroed by apply_kernel each call
__device__ int g_ps[N_NODES];           // per-element block-local exclusive prescan
__device__ int g_bsum[SCAN_BLOCKS];     // per-scan-block totals
__device__ int g_boff[SCAN_BLOCKS];     // exclusive scan of block totals
__device__ int g_row_ptr[N_NODES + 1];  // CSR row pointers (by dst)
__device__ int g_cursor[N_NODES];       // fill cursors for reorder
__device__ int g_esrc[N_EDGES];         // src index of each edge, grouped by dst
__device__ __align__(16) float2 g_Bp[64 * 64];  // k-pair-packed B: [kp][c]=(B[2kp][c],B[2kp+1][c])
__device__ float g_bm[DIM];
__device__ float g_bs[DIM];

// packed f32x2 FMA: d.lo += a.lo*b.lo ; d.hi += a.hi*b.hi
__device__ __forceinline__ void fma2(unsigned long long& d,
                                     unsigned long long a,
                                     unsigned long long b) {
    asm("fma.rn.f32x2 %0, %1, %2, %0;" : "+l"(d) : "l"(a), "l"(b));
}
__device__ __forceinline__ float pair_sum(unsigned long long v) {
    return __uint_as_float((unsigned)(v & 0xffffffffull)) +
           __uint_as_float((unsigned)(v >> 32));
}

// ---------------- kernel 1: collapse bases into packed weights (proven ~5us)
__global__ __launch_bounds__(256) void weights_kernel(
    const float* __restrict__ wm, const float* __restrict__ bm,
    const float* __restrict__ ws, const float* __restrict__ bs,
    const float* __restrict__ lc) {
    __shared__ float c[NBASES];
    if (threadIdx.x < NBASES) c[threadIdx.x] = lc[threadIdx.x];
    __syncthreads();
    if (blockIdx.x < 16) {
        int idx = blockIdx.x * 256 + threadIdx.x;   // 0..4095
        int kp = idx >> 6;
        int o  = idx & 63;
        const float* base = (kp < 32) ? wm : ws;
        int i0 = (kp < 32) ? 2 * kp : 2 * (kp - 32);
        const float4* p0 = reinterpret_cast<const float4*>(&base[((size_t)i0 * 64 + o) * NBASES]);
        const float4* p1 = reinterpret_cast<const float4*>(&base[((size_t)(i0 + 1) * 64 + o) * NBASES]);
        float lo = 0.f, hi = 0.f;
        #pragma unroll
        for (int q = 0; q < 4; q++) {
            float4 a0 = __ldg(&p0[q]);
            float4 a1 = __ldg(&p1[q]);
            lo = fmaf(a0.x, c[4*q+0], lo); lo = fmaf(a0.y, c[4*q+1], lo);
            lo = fmaf(a0.z, c[4*q+2], lo); lo = fmaf(a0.w, c[4*q+3], lo);
            hi = fmaf(a1.x, c[4*q+0], hi); hi = fmaf(a1.y, c[4*q+1], hi);
            hi = fmaf(a1.z, c[4*q+2], hi); hi = fmaf(a1.w, c[4*q+3], hi);
        }
        g_Bp[idx] = make_float2(lo, hi);
    } else if (threadIdx.x < DIM) {
        int tid = threadIdx.x;
        float am = 0.f, as = 0.f;
        #pragma unroll
        for (int b = 0; b < NBASES; b++) {
            am = fmaf(__ldg(&bm[tid * NBASES + b]), c[b], am);
            as = fmaf(__ldg(&bs[tid * NBASES + b]), c[b], as);
        }
        g_bm[tid] = am;
        g_bs[tid] = as;
    }
}

// ---------------- kernel 2: histogram of dst ------------------------------
__global__ __launch_bounds__(256) void hist_kernel(const int* __restrict__ ei) {
    int t = blockIdx.x * 256 + threadIdx.x;
    if (t < N_EDGES) atomicAdd(&g_cnt[__ldg(&ei[N_EDGES + t])], 1);
}

// ---------------- kernel 3a: per-block exclusive prescan of g_cnt ----------
__global__ __launch_bounds__(1024) void scan1_kernel() {
    __shared__ int wsum[32];
    int i = blockIdx.x * 1024 + threadIdx.x;
    int v = (i < N_NODES) ? g_cnt[i] : 0;
    int lane = threadIdx.x & 31, wid = threadIdx.x >> 5;
    int s = v;                                     // inclusive warp scan
    #pragma unroll
    for (int o = 1; o < 32; o <<= 1) {
        int t = __shfl_up_sync(0xffffffffu, s, o);
        if (lane >= o) s += t;
    }
    if (lane == 31) wsum[wid] = s;
    __syncthreads();
    if (wid == 0) {
        int ws = wsum[lane];
        #pragma unroll
        for (int o = 1; o < 32; o <<= 1) {
            int t = __shfl_up_sync(0xffffffffu, ws, o);
            if (lane >= o) ws += t;
        }
        wsum[lane] = ws;                           // inclusive warp totals
    }
    __syncthreads();
    int woff = (wid > 0) ? wsum[wid - 1] : 0;
    if (i < N_NODES) g_ps[i] = woff + s - v;       // exclusive
    if (threadIdx.x == 1023) g_bsum[blockIdx.x] = wsum[31];
}

// ---------------- kernel 3b: exclusive scan of the 98 block totals ---------
__global__ __launch_bounds__(128) void scan2_kernel() {
    __shared__ int wsum[4];
    int lane = threadIdx.x & 31, wid = threadIdx.x >> 5;
    int v = (threadIdx.x < SCAN_BLOCKS) ? g_bsum[threadIdx.x] : 0;
    int s = v;
    #pragma unroll
    for (int o = 1; o < 32; o <<= 1) {
        int t = __shfl_up_sync(0xffffffffu, s, o);
        if (lane >= o) s += t;
    }
    if (lane == 31) wsum[wid] = s;
    __syncthreads();
    if (wid == 0 && lane < 4) {
        int ws = wsum[lane];
        #pragma unroll
        for (int o = 1; o < 4; o <<= 1) {
            int t = __shfl_up_sync(0x0000000fu, ws, o);
            if (lane >= o) ws += t;
        }
        wsum[lane] = ws;
    }
    __syncthreads();
    int woff = (wid > 0) ? wsum[wid - 1] : 0;
    if (threadIdx.x < SCAN_BLOCKS) g_boff[threadIdx.x] = woff + s - v;
}

// ---------------- kernel 3c: apply offsets -> row_ptr + cursor; zero cnt ---
__global__ __launch_bounds__(256) void apply_kernel() {
    int i = blockIdx.x * 256 + threadIdx.x;
    if (i < N_NODES) {
        int rp = g_ps[i] + g_boff[i >> 10];
        g_row_ptr[i] = rp;
        g_cursor[i]  = rp;
        g_cnt[i]     = 0;                          // ready for next call's hist
    }
    if (i == 0) g_row_ptr[N_NODES] = N_EDGES;
}

// ---------------- kernel 4: reorder edge srcs into dst-grouped CSR ---------
__global__ __launch_bounds__(256) void reorder_kernel(const int* __restrict__ ei) {
    int t = blockIdx.x * 256 + threadIdx.x;
    if (t >= N_EDGES) return;
    int src = __ldg(&ei[t]);
    int dst = __ldg(&ei[N_EDGES + t]);
    int pos = atomicAdd(&g_cursor[dst], 1);
    g_esrc[pos] = src;
}

// ---------------- kernel 5: fused gather + GEMM + bias + L2-normalize ------
// Phase 1: 64 groups x 4 threads gather-sum x[src] rows into 16KB smem tile.
// Phase 2: R5-proven f32x2 GEMM; aggregate half from SMEM (LDS, 29cyc) —
//          attacks the L2-latency exposure that pinned prior versions at 93us.
// No g_S scratch, no scatter atomics, no self-clean. deg from CSR offsets.
__global__ __launch_bounds__(256, 2) void gather_gemm_kernel(
    const float* __restrict__ x, float* __restrict__ out) {
    __shared__ __align__(16) float sAgg[64 * 64];  // 16KB aggregate tile
    __shared__ float sdeg[64];

    const int tid = threadIdx.x;
    const int node0 = blockIdx.x * 64;
    const float4* __restrict__ x4 = reinterpret_cast<const float4*>(x);

    // ---- Phase 1: gather ----
    {
        int g = tid >> 2;          // node group 0..63
        int q = tid & 3;           // quarter of the 64-float row
        int node = node0 + g;
        float4 a0 = make_float4(0.f, 0.f, 0.f, 0.f), a1 = a0, a2 = a0, a3 = a0;
        if (node < N_NODES) {
            int start = __ldg(&g_row_ptr[node]);
            int end   = __ldg(&g_row_ptr[node + 1]);
            if (q == 0) sdeg[g] = (float)(end - start);
            int e = start;
            int src = (e < end) ? __ldg(&g_esrc[e]) : 0;
            while (e < end) {
                int nsrc = (e + 1 < end) ? __ldg(&g_esrc[e + 1]) : 0;  // prefetch
                const float4* p = &x4[(size_t)src * 16 + q * 4];
                float4 v0 = __ldg(p), v1 = __ldg(p + 1), v2 = __ldg(p + 2), v3 = __ldg(p + 3);
                a0.x += v0.x; a0.y += v0.y; a0.z += v0.z; a0.w += v0.w;
                a1.x += v1.x; a1.y += v1.y; a1.z += v1.z; a1.w += v1.w;
                a2.x += v2.x; a2.y += v2.y; a2.z += v2.z; a2.w += v2.w;
                a3.x += v3.x; a3.y += v3.y; a3.z += v3.z; a3.w += v3.w;
                src = nsrc; e++;
            }
        } else if (q == 0) sdeg[g] = 0.f;
        float4* sa = reinterpret_cast<float4*>(&sAgg[g * 64 + q * 16]);
        sa[0] = a0; sa[1] = a1; sa[2] = a2; sa[3] = a3;
    }
    __syncthreads();

    // ---- Phase 2: GEMM ----
    const int jj = tid & 15;   // column group: cols j0..j0+3
    const int nn = tid >> 4;   // row group:   rows n0..n0+3
    const int j0 = jj * 4;
    const int n0 = nn * 4;

    const ulonglong2* A1 = reinterpret_cast<const ulonglong2*>(sAgg);  // 16 ull2/row
    const ulonglong2* __restrict__ X2  = reinterpret_cast<const ulonglong2*>(x);
    const ulonglong2* __restrict__ Bp2 = reinterpret_cast<const ulonglong2*>(g_Bp);
    const int bbase = j0 >> 1;  // ull2 index within a Bp row (32 ull2/row)

    int node[4];
    #pragma unroll
    for (int r = 0; r < 4; r++)
        node[r] = min(node0 + n0 + r, N_NODES - 1);  // clamp; uniform per 16-lane group

    unsigned long long acc[4][4];
    #pragma unroll
    for (int r = 0; r < 4; r++)
        #pragma unroll
        for (int c2 = 0; c2 < 4; c2++) acc[r][c2] = 0ull;

    // K half 1: A = aggregate rows (smem), B pair-rows kp 0..31
    #pragma unroll 4
    for (int k4 = 0; k4 < 16; k4++) {
        ulonglong2 av[4];
        #pragma unroll
        for (int r = 0; r < 4; r++)
            av[r] = A1[(n0 + r) * 16 + k4];
        #pragma unroll
        for (int p = 0; p < 2; p++) {
            int kp = k4 * 2 + p;
            ulonglong2 b01 = __ldg(&Bp2[kp * 32 + bbase]);
            ulonglong2 b23 = __ldg(&Bp2[kp * 32 + bbase + 1]);
            #pragma unroll
            for (int r = 0; r < 4; r++) {
                unsigned long long a = p ? av[r].y : av[r].x;
                fma2(acc[r][0], a, b01.x);
                fma2(acc[r][1], a, b01.y);
                fma2(acc[r][2], a, b23.x);
                fma2(acc[r][3], a, b23.y);
            }
        }
    }
    // K half 2: A = x rows (global), B pair-rows kp 32..63
    #pragma unroll 4
    for (int k4 = 0; k4 < 16; k4++) {
        ulonglong2 av[4];
        #pragma unroll
        for (int r = 0; r < 4; r++)
            av[r] = __ldg(&X2[(size_t)node[r] * 16 + k4]);
        #pragma unroll
        for (int p = 0; p < 2; p++) {
            int kp = 32 + k4 * 2 + p;
            ulonglong2 b01 = __ldg(&Bp2[kp * 32 + bbase]);
            ulonglong2 b23 = __ldg(&Bp2[kp * 32 + bbase + 1]);
            #pragma unroll
            for (int r = 0; r < 4; r++) {
                unsigned long long a = p ? av[r].y : av[r].x;
                fma2(acc[r][0], a, b01.x);
                fma2(acc[r][1], a, b01.y);
                fma2(acc[r][2], a, b23.x);
                fma2(acc[r][3], a, b23.y);
            }
        }
    }

    // biases for this thread's 4 columns
    float bmj[4], bsj[4];
    #pragma unroll
    for (int c = 0; c < 4; c++) {
        bmj[c] = __ldg(&g_bm[j0 + c]);
        bsj[c] = __ldg(&g_bs[j0 + c]);
    }

    // Epilogue: fold halves, bias, row L2-norm (reduce across 16 jj lanes), store.
    #pragma unroll
    for (int r = 0; r < 4; r++) {
        float deg = sdeg[n0 + r];
        float o[4];
        #pragma unroll
        for (int c = 0; c < 4; c++)
            o[c] = pair_sum(acc[r][c]) + deg * bmj[c] + bsj[c];
        float ss = o[0] * o[0] + o[1] * o[1] + o[2] * o[2] + o[3] * o[3];
        #pragma unroll
        for (int off = 8; off > 0; off >>= 1)
            ss += __shfl_xor_sync(0xffffffffu, ss, off);   // stays within 16-lane half
        float inv = 1.0f / fmaxf(sqrtf(ss), 1e-12f);
        if (node0 + n0 + r < N_NODES) {
            float4 ov = make_float4(o[0] * inv, o[1] * inv, o[2] * inv, o[3] * inv);
            reinterpret_cast<float4*>(out)[(size_t)node[r] * 16 + jj] = ov;
        }
    }
}

// ---------------- launch ----------------------------------------------------
extern "C" void kernel_launch(void* const* d_in, const int* in_sizes, int n_in,
                              void* d_out, int out_size) {
    const float* x  = (const float*)d_in[0];
    const int*   ei = (const int*)d_in[1];
    const float* wm = (const float*)d_in[2];
    const float* bm = (const float*)d_in[3];
    const float* ws = (const float*)d_in[4];
    const float* bs = (const float*)d_in[5];
    const float* lc = (const float*)d_in[6];
    float* out = (float*)d_out;

    const int eblocks = (N_EDGES + 255) / 256;
    const int nblocks = (N_NODES + 255) / 256;

    weights_kernel<<<17, 256>>>(wm, bm, ws, bs, lc);
    hist_kernel<<<eblocks, 256>>>(ei);            // g_cnt zero: BSS / prev apply
    scan1_kernel<<<SCAN_BLOCKS, 1024>>>();
    scan2_kernel<<<1, 128>>>();
    apply_kernel<<<nblocks, 256>>>();             // row_ptr + cursor; zeroes cnt
    reorder_kernel<<<eblocks, 256>>>(ei);         // dst-grouped src list
    gather_gemm_kernel<<<N_TILES, 256>>>(x, out); // gather + GEMM + normalize
}